// round 16
// baseline (speedup 1.0000x reference)
#include <cuda_runtime.h>
#include <cuda_fp16.h>
#include <math.h>
#include <cstdint>

#define B 8192

typedef unsigned long long ull;

// ---------------- packed f32x2 helpers ----------------
__device__ __forceinline__ ull pack2(float v) {
    ull r; asm("mov.b64 %0, {%1, %1};" : "=l"(r) : "f"(v)); return r;
}
__device__ __forceinline__ void fma2(ull& d, ull a, ull b) {
    asm("fma.rn.f32x2 %0, %1, %2, %0;" : "+l"(d) : "l"(a), "l"(b));
}
__device__ __forceinline__ float2 unpack2(ull v) {
    float2 f; asm("mov.b64 {%0, %1}, %2;" : "=f"(f.x), "=f"(f.y) : "l"(v)); return f;
}

// ---------------- fp16 pack: u32 = {lo: h(v0), hi: h(v1)} ----------------
__device__ __forceinline__ uint32_t hpack(float v0, float v1) {
    __half2 h = __floats2half2_rn(v0, v1);
    return *(uint32_t*)&h;
}

// ---------------- mma.sync m16n8k16 fp16 (f32 acc) ----------------
__device__ __forceinline__ void mma_fp16(float* c, const uint32_t* a, const uint32_t* b) {
    asm volatile(
        "mma.sync.aligned.m16n8k16.row.col.f32.f16.f16.f32 "
        "{%0,%1,%2,%3}, {%4,%5,%6,%7}, {%8,%9}, {%0,%1,%2,%3};"
        : "+f"(c[0]), "+f"(c[1]), "+f"(c[2]), "+f"(c[3])
        : "r"(a[0]), "r"(a[1]), "r"(a[2]), "r"(a[3]), "r"(b[0]), "r"(b[1]));
}

// ---------------- global scratch ----------------
__device__ __align__(16) uint32_t g_fh[B * 800];   // feat fp16 pairs [b][800]
__device__ __align__(16) uint32_t g_wfrag[18 * 8 * 32 * 2];    // conv2 B frags
__device__ __align__(16) uint32_t g_hfrag[100 * 7 * 32 * 2];   // head B frags

// ==================== prep: conv2 w fragments (fp16) ====================
__global__ void prep_wfrag_kernel(const float* __restrict__ w2) {
    int i = blockIdx.x * blockDim.x + threadIdx.x;
    if (i >= 18 * 8 * 32) return;
    const int ks = i >> 8;
    const int r  = i & 255;
    const int nt = r >> 5;
    const int lane = r & 31;
    const int g  = lane >> 2;
    const int tq = lane & 3;
    const int co = nt * 8 + g;
    const int k0 = ks * 16 + 2 * tq;
    const int k1 = k0 + 8;
    uint32_t* o = g_wfrag + (size_t)i * 2;
    o[0] = hpack(w2[k0 * 64 + co], w2[(k0 + 1) * 64 + co]);
    o[1] = hpack(w2[k1 * 64 + co], w2[(k1 + 1) * 64 + co]);
}

// ==================== prep: head w fragments ====================
__device__ __forceinline__ float head_w(const float* gw, const float* ew, int d, int j) {
    if (j < 5) return gw[d * 5 + j];
    const int e = (j - 5) / 10, c = (j - 5) % 10;
    return ew[(e * 1600 + d) * 10 + c];
}
__global__ void prep_hfrag_kernel(const float* __restrict__ gw,
                                  const float* __restrict__ ew) {
    int i = blockIdx.x * blockDim.x + threadIdx.x;
    if (i >= 100 * 7 * 32) return;
    const int ks = i / 224;
    const int rr = i - ks * 224;
    const int nt = rr >> 5;
    const int lane = rr & 31;
    const int g  = lane >> 2;
    const int tq = lane & 3;
    const int col = nt * 8 + g;
    const int k0 = ks * 16 + 2 * tq;
    const int k1 = k0 + 8;
    uint32_t* o = g_hfrag + (size_t)i * 2;
    o[0] = hpack(head_w(gw, ew, k0, col), head_w(gw, ew, k0 + 1, col));
    o[1] = hpack(head_w(gw, ew, k1, col), head_w(gw, ew, k1 + 1, col));
}

// ==================== K1: conv1(FFMA2) + conv2(mma.sync fp16, warp=ntile balanced) ====================
#define SM_HH  0
#define SM_WF  11504
#define SM_X   48368
#define SM_W1  51504
#define SM_B1  52656
#define SM_B2  52784
#define SM_TOTAL 53040
#define SM_D   SM_WF
#define HST 17

__global__ __launch_bounds__(256, 3) void conv_mma_kernel(
    const float* __restrict__ x,
    const float* __restrict__ w1,
    const float* __restrict__ b1,
    const float* __restrict__ b2)
{
    extern __shared__ char smc[];
    uint32_t* s_hh = (uint32_t*)(smc + SM_HH);
    const uint2* s_wf = (const uint2*)(smc + SM_WF);
    float* s_x  = (float*)(smc + SM_X);
    float* s_w1 = (float*)(smc + SM_W1);
    float* s_b1 = (float*)(smc + SM_B1);
    float* s_b2 = (float*)(smc + SM_B2);
    float* s_D  = (float*)(smc + SM_D);

    const int t    = threadIdx.x;
    const int wid  = t >> 5;
    const int lane = t & 31;
    const int bb   = blockIdx.x;

    // ---- stage ----
    {
        const float* xi = x + bb * 784;
        for (int i = t; i < 784; i += 256) s_x[i] = xi[i];
        for (int i = t; i < 288; i += 256) s_w1[i] = w1[i];
        if (t < 32) s_b1[t] = b1[t];
        else if (t < 96) s_b2[t - 32] = b2[t - 32];
        const float4* src = (const float4*)g_wfrag;
        float4* dst = (float4*)(smc + SM_WF);
        for (int i = t; i < 2304; i += 256) dst[i] = src[i];
    }
    __syncthreads();

    // ---- conv1 + relu + pool -> s_hh (fp16 pairs) ----
    for (int i = t; i < 676; i += 256) {
        const int cell = i >> 2;
        const int c0   = (i & 3) * 8;
        const int qy = cell / 13, qx = cell - qy * 13;
        const float* xb = s_x + (2 * qy) * 28 + 2 * qx;

        ull a1[4][4];
        #pragma unroll
        for (int p = 0; p < 4; p++)
            #pragma unroll
            for (int j = 0; j < 4; j++) a1[p][j] = 0ULL;

        #pragma unroll
        for (int ky = 0; ky < 3; ky++)
            #pragma unroll
            for (int kx = 0; kx < 3; kx++) {
                const float* xp = xb + ky * 28 + kx;
                const ull xpk[4] = { pack2(xp[0]), pack2(xp[1]), pack2(xp[28]), pack2(xp[29]) };
                const ulonglong2* wq = (const ulonglong2*)(s_w1 + (ky * 3 + kx) * 32 + c0);
                const ulonglong2 wA = wq[0], wB = wq[1];
                const ull wv[4] = { wA.x, wA.y, wB.x, wB.y };
                #pragma unroll
                for (int p = 0; p < 4; p++)
                    #pragma unroll
                    for (int j = 0; j < 4; j++) fma2(a1[p][j], xpk[p], wv[j]);
            }
        uint32_t* hh = s_hh + cell * HST + (c0 >> 1);
        #pragma unroll
        for (int j = 0; j < 4; j++) {
            const float2 u0 = unpack2(a1[0][j]), u1 = unpack2(a1[1][j]);
            const float2 u2 = unpack2(a1[2][j]), u3 = unpack2(a1[3][j]);
            const float v0 = fmaxf(fmaxf(fmaxf(u0.x, u1.x), fmaxf(u2.x, u3.x)) + s_b1[c0 + 2*j],     0.0f);
            const float v1 = fmaxf(fmaxf(fmaxf(u0.y, u1.y), fmaxf(u2.y, u3.y)) + s_b1[c0 + 2*j + 1], 0.0f);
            hh[j] = hpack(v0, v1);
        }
    }
    __syncthreads();

    // ---- conv2 GEMM: M=112 x N=64 x K=288; warp = n-tile (8 warps, balanced SMSPs) ----
    const int g  = lane >> 2;
    const int tq = lane & 3;

    float acc[7][4];                       // 7 m-tiles for this warp's n-tile
    #pragma unroll
    for (int mt = 0; mt < 7; mt++)
        #pragma unroll
        for (int q = 0; q < 4; q++) acc[mt][q] = 0.0f;

    // row -> h1 cell mapping per m-tile
    int crow0[7], crow1[7];
    #pragma unroll
    for (int mt = 0; mt < 7; mt++) {
        const int r0 = mt * 16 + g, r1 = r0 + 8;
        crow0[mt] = (r0 < 100) ? (r0 / 10) * 13 + (r0 % 10) : 0;
        crow1[mt] = (r1 < 100) ? (r1 / 10) * 13 + (r1 % 10) : 0;
    }

    #pragma unroll 1
    for (int ks = 0; ks < 18; ks++) {
        const int tap = ks >> 1;
        const int ty = tap / 3, tx = tap - ty * 3;
        const int toff = ty * 13 + tx;
        const int j0 = ((ks & 1) << 3) + tq;

        // B fragment: single LDS.64 (this warp's n-tile)
        const uint2 f = s_wf[(ks * 8 + wid) * 32 + lane];
        uint32_t bfr[2] = { f.x, f.y };

        #pragma unroll
        for (int mt = 0; mt < 7; mt++) {
            const uint32_t* hh0 = s_hh + (crow0[mt] + toff) * HST;
            const uint32_t* hh1 = s_hh + (crow1[mt] + toff) * HST;
            uint32_t ah[4];
            ah[0] = hh0[j0];      ah[1] = hh1[j0];
            ah[2] = hh0[j0 + 4];  ah[3] = hh1[j0 + 4];
            mma_fp16(acc[mt], ah, bfr);
        }
    }

    // ---- write D to smem (aliases WF -> barrier first) ----
    __syncthreads();
    {
        const int col = wid * 8 + 2 * tq;
        #pragma unroll
        for (int mt = 0; mt < 7; mt++) {
            const int dr0 = mt * 16 + g;
            *(float2*)(s_D + dr0 * 66 + col)       = make_float2(acc[mt][0], acc[mt][1]);
            *(float2*)(s_D + (dr0 + 8) * 66 + col) = make_float2(acc[mt][2], acc[mt][3]);
        }
    }
    __syncthreads();

    // ---- maxpool + bias + relu -> g_fh (fp16 pairs only) ----
    if (t < 200) {
        const int cg = t / 25;
        const int pc = t - cg * 25;
        const int co0 = cg * 8;
        const int qy = pc / 5, qx = pc - qy * 5;
        const float* r0p = s_D + ((2 * qy) * 10 + 2 * qx) * 66 + co0;
        const float* r1p = r0p + 66;
        const float* r2p = s_D + ((2 * qy + 1) * 10 + 2 * qx) * 66 + co0;
        const float* r3p = r2p + 66;
        uint32_t* fh = g_fh + bb * 800 + pc * 32 + (co0 >> 1);
        #pragma unroll
        for (int j = 0; j < 8; j += 2) {
            const float v0 = fmaxf(fmaxf(fmaxf(r0p[j],   r1p[j]),   fmaxf(r2p[j],   r3p[j]))   + s_b2[co0 + j],     0.0f);
            const float v1 = fmaxf(fmaxf(fmaxf(r0p[j+1], r1p[j+1]), fmaxf(r2p[j+1], r3p[j+1])) + s_b2[co0 + j + 1], 0.0f);
            fh[j >> 1] = hpack(v0, v1);
        }
    }
}

// ==================== K2: head — barrier-free register-pipelined, single fp16 term ====================
// 256 blocks x 32 rows; warps: s = w>>1 (k-split, 25 rounds), mt = w&1 (m-tile of 16)
__global__ __launch_bounds__(256) void moe_head_kernel(
    const float* __restrict__ gb,
    const float* __restrict__ eb,
    float* __restrict__ out)
{
    __shared__ float s_p[6 * 896];
    __shared__ float s_l[32 * 57];
    __shared__ float s_bias[56];

    const int t    = threadIdx.x;
    const int wid  = t >> 5;
    const int lane = t & 31;
    const int s    = wid >> 1;
    const int mt   = wid & 1;
    const int g    = lane >> 2;
    const int tq   = lane & 3;
    const int row0 = blockIdx.x * 32;

    if (t < 56) s_bias[t] = (t < 5) ? gb[t] : eb[t - 5];

    float acc[7][4];
    #pragma unroll
    for (int nt = 0; nt < 7; nt++)
        #pragma unroll
        for (int q = 0; q < 4; q++) acc[nt][q] = 0.0f;

    const int rowa = row0 + mt * 16 + g;
    const uint32_t* A0h = g_fh + (size_t)rowa * 800 + s * 200 + tq;
    const uint32_t* A1h = A0h + 8 * 800;
    const uint2* Bp = (const uint2*)g_hfrag + (size_t)(s * 25) * 224 + lane;

    uint32_t ah[2][4];
    uint2 bf[2][7];

    // prefetch round 0
    {
        ah[0][0] = A0h[0];  ah[0][1] = A1h[0];  ah[0][2] = A0h[4];  ah[0][3] = A1h[4];
        #pragma unroll
        for (int nt = 0; nt < 7; nt++) bf[0][nt] = Bp[nt * 32];
    }

    #pragma unroll 1
    for (int r = 0; r < 25; r++) {
        const int cur = r & 1, nxt = cur ^ 1;
        if (r < 24) {
            const int ro = (r + 1) * 8;
            ah[nxt][0] = A0h[ro];      ah[nxt][1] = A1h[ro];
            ah[nxt][2] = A0h[ro + 4];  ah[nxt][3] = A1h[ro + 4];
            #pragma unroll
            for (int nt = 0; nt < 7; nt++) bf[nxt][nt] = Bp[(r + 1) * 224 + nt * 32];
        }
        #pragma unroll
        for (int nt = 0; nt < 7; nt++) {
            uint32_t bfr[2] = { bf[cur][nt].x, bf[cur][nt].y };
            mma_fp16(acc[nt], ah[cur], bfr);
        }
    }

    // ---- k-split reduction via smem ----
    if (s > 0) {
        float* pp = s_p + ((s - 1) * 2 + mt) * 896;
        #pragma unroll
        for (int nt = 0; nt < 7; nt++)
            #pragma unroll
            for (int q = 0; q < 4; q++)
                pp[(nt * 4 + q) * 32 + lane] = acc[nt][q];
    }
    __syncthreads();
    if (s == 0) {
        #pragma unroll
        for (int q3 = 0; q3 < 3; q3++) {
            const float* pp = s_p + (q3 * 2 + mt) * 896;
            #pragma unroll
            for (int nt = 0; nt < 7; nt++)
                #pragma unroll
                for (int q = 0; q < 4; q++)
                    acc[nt][q] += pp[(nt * 4 + q) * 32 + lane];
        }
        const int row = mt * 16 + g;
        #pragma unroll
        for (int nt = 0; nt < 7; nt++) {
            const int col = nt * 8 + 2 * tq;
            s_l[row * 57 + col]           = acc[nt][0] + s_bias[col];
            s_l[row * 57 + col + 1]       = acc[nt][1] + s_bias[col + 1];
            s_l[(row + 8) * 57 + col]     = acc[nt][2] + s_bias[col];
            s_l[(row + 8) * 57 + col + 1] = acc[nt][3] + s_bias[col + 1];
        }
    }
    __syncthreads();

    // ---- per-row MoE epilogue ----
    if (t < 32) {
        const float* L = s_l + t * 57;
        float p[5];
        float gm = -1e30f;
        #pragma unroll
        for (int e = 0; e < 5; e++) gm = fmaxf(gm, L[e]);
        float gsum = 0.0f;
        #pragma unroll
        for (int e = 0; e < 5; e++) { p[e] = expf(L[e] - gm); gsum += p[e]; }
        const float ginv = 1.0f / gsum;
        #pragma unroll
        for (int e = 0; e < 5; e++) p[e] *= ginv;

        int idx[5] = {0, 1, 2, 3, 4};
        #pragma unroll
        for (int a = 0; a < 3; a++) {
            int best = a;
            #pragma unroll
            for (int q = a + 1; q < 5; q++)
                if (p[idx[q]] > p[idx[best]]) best = q;
            const int tmp = idx[a]; idx[a] = idx[best]; idx[best] = tmp;
        }

        float comb[10];
        #pragma unroll
        for (int c = 0; c < 10; c++) {
            float v = 0.0f;
            #pragma unroll
            for (int k = 0; k < 3; k++)
                v = fmaf(p[idx[k]], L[5 + idx[k] * 10 + c], v);
            comb[c] = v;
        }
        float cm = -1e30f;
        #pragma unroll
        for (int c = 0; c < 10; c++) cm = fmaxf(cm, comb[c]);
        float cs = 0.0f;
        float ex[10];
        #pragma unroll
        for (int c = 0; c < 10; c++) { ex[c] = expf(comb[c] - cm); cs += ex[c]; }
        const float inv = 1.0f / cs;
        float* o = out + (row0 + t) * 10;
        #pragma unroll
        for (int c = 0; c < 10; c++) o[c] = ex[c] * inv;
    }
}

// ==================== launcher ====================
extern "C" void kernel_launch(void* const* d_in, const int* in_sizes, int n_in,
                              void* d_out, int out_size) {
    const float* x  = (const float*)d_in[0];
    const float* w1 = (const float*)d_in[1];
    const float* b1 = (const float*)d_in[2];
    const float* w2 = (const float*)d_in[3];
    const float* b2 = (const float*)d_in[4];
    const float* gw = (const float*)d_in[5];
    const float* gb = (const float*)d_in[6];
    const float* ew = (const float*)d_in[7];
    const float* eb = (const float*)d_in[8];
    float* out = (float*)d_out;

    cudaFuncSetAttribute(conv_mma_kernel,
                         cudaFuncAttributeMaxDynamicSharedMemorySize, SM_TOTAL);

    prep_wfrag_kernel<<<(18 * 8 * 32 + 255) / 256, 256>>>(w2);
    prep_hfrag_kernel<<<(100 * 7 * 32 + 255) / 256, 256>>>(gw, ew);
    conv_mma_kernel<<<B, 256, SM_TOTAL>>>(x, w1, b1, b2);
    moe_head_kernel<<<B / 32, 256>>>(gb, eb, out);
}